// round 16
// baseline (speedup 1.0000x reference)
#include <cuda_runtime.h>
#include <cstdint>

#define TAGS 2048
#define NCTA 128
#define ROWS 16          // NCTA*ROWS == TAGS
#define NTHR 256
#define NWORD (TAGS / 2) // 1024 u64 words: {tag(hi32) | bf16x2 p-pair(lo32)}
#define NEGV -10000.0f

__device__ unsigned long long g_w[2][NWORD];

__global__ void init_kernel() {
    int j = blockIdx.x * blockDim.x + threadIdx.x;
    if (j < NWORD) {
        // step-0 p = exp(fv0 - 0) = {1, 0, 0, ...}; tag 0
        unsigned pay = (j == 0) ? 0x00003F80u : 0u;   // lo=bf16(1.0)@col0, hi=bf16(0)@col1
        g_w[0][j] = (unsigned long long)pay;          // tag 0 in high bits
        g_w[1][j] = 0x8000000000000000ull;            // tag 0x80000000: never matches
    }
}

__device__ __forceinline__ float bflo(unsigned u) { return __uint_as_float(u << 16); }
__device__ __forceinline__ float bfhi(unsigned u) { return __uint_as_float(u & 0xFFFF0000u); }
__device__ __forceinline__ unsigned bfpack(float lo, float hi) {
    unsigned u;
    asm("cvt.rn.bf16x2.f32 %0, %1, %2;" : "=r"(u) : "f"(hi), "f"(lo));  // first src = high
    return u;
}
__device__ __forceinline__ unsigned long long ldacq(const unsigned long long* p) {
    unsigned long long v;
    asm volatile("ld.acquire.gpu.global.b64 %0, [%1];" : "=l"(v) : "l"(p) : "memory");
    return v;
}
__device__ __forceinline__ void exch_rel(unsigned long long* p, unsigned long long v) {
    unsigned long long d;
    asm volatile("atom.release.gpu.global.exch.b64 %0, [%1], %2;"
                 : "=l"(d) : "l"(p), "l"(v) : "memory");
}
__device__ __forceinline__ unsigned tag_of(unsigned long long v) { return (unsigned)(v >> 32); }

// ---------------- persistent main kernel ------------------------------------
extern "C" __global__ void __launch_bounds__(NTHR, 1)
crf_main(const float* __restrict__ h, const float* __restrict__ trans,
         float* __restrict__ out, int S) {
    __shared__ float2 part2[2][8 * NTHR];   // parity-double-buffered reduction scratch
    __shared__ float  s_rmax[ROWS];
    __shared__ float  s_D[2];               // parity-double-buffered shift increment

    const int b = blockIdx.x, t = threadIdx.x;
    const int lane = t & 31, w = t >> 5;
    const int row0 = b * ROWS;
    const int c0 = 8 * t;                // this thread's 8 columns

    // ---- prologue: build E = exp(trans - rowmax) in REGISTERS (f32) --------
    float E[ROWS][8];
    {
        float lm[ROWS];
        #pragma unroll
        for (int r = 0; r < ROWS; r++) {
            const float4* tp = (const float4*)(trans + (size_t)(row0 + r) * TAGS + c0);
            float4 a = __ldg(tp), bb = __ldg(tp + 1);
            E[r][0] = a.x;  E[r][1] = a.y;  E[r][2] = a.z;  E[r][3] = a.w;
            E[r][4] = bb.x; E[r][5] = bb.y; E[r][6] = bb.z; E[r][7] = bb.w;
            lm[r] = fmaxf(fmaxf(fmaxf(a.x, a.y), fmaxf(a.z, a.w)),
                          fmaxf(fmaxf(bb.x, bb.y), fmaxf(bb.z, bb.w)));
        }
        #pragma unroll
        for (int pr = 0; pr < 8; pr++)
            part2[0][pr * NTHR + t] = make_float2(lm[2 * pr], lm[2 * pr + 1]);
        __syncthreads();
        float2 m = make_float2(-3.4e38f, -3.4e38f);
        for (int i = lane; i < NTHR; i += 32) {
            float2 v = part2[0][w * NTHR + i];
            m.x = fmaxf(m.x, v.x); m.y = fmaxf(m.y, v.y);
        }
        #pragma unroll
        for (int o = 16; o; o >>= 1) {
            m.x = fmaxf(m.x, __shfl_xor_sync(~0u, m.x, o));
            m.y = fmaxf(m.y, __shfl_xor_sync(~0u, m.y, o));
        }
        if (lane == 0) { s_rmax[2 * w] = m.x; s_rmax[2 * w + 1] = m.y; }
        __syncthreads();
        #pragma unroll
        for (int r = 0; r < ROWS; r++) {
            float rm = s_rmax[r];
            #pragma unroll
            for (int q = 0; q < 8; q++)
                E[r][q] = __expf(E[r][q] - rm);
        }
    }
    const float2 myrmax = make_float2(s_rmax[2 * w], s_rmax[2 * w + 1]);

    // emit prefetch for step 0 (lane0 of warp w owns rows 2w, 2w+1)
    float2 emit = make_float2(0.f, 0.f);
    if (lane == 0) emit = __ldg((const float2*)(h + row0 + 2 * w));
    __syncthreads();

    float Vacc = 0.0f;   // local copy of V_{s} = sum of agreed D increments

    // ---- main sequential scan: ONE __syncthreads per step ----
    for (int s = 0; s < S; s++) {
        const int par = s & 1;

        // prefetch next step's emissions
        float2 emitN = emit;
        if (lane == 0 && s + 1 < S)
            emitN = __ldg((const float2*)(h + (size_t)(s + 1) * TAGS + row0 + 2 * w));

        // poll own 4 tagged words until all carry tag s (acquire loads)
        const unsigned long long* base = g_w[par] + 4 * t;
        const unsigned tgt = (unsigned)s;
        unsigned long long w0, w1, w2, w3;
        for (;;) {
            w0 = ldacq(base);     w1 = ldacq(base + 1);
            w2 = ldacq(base + 2); w3 = ldacq(base + 3);
            if (tag_of(w0) == tgt && tag_of(w1) == tgt &&
                tag_of(w2) == tgt && tag_of(w3) == tgt) break;
        }
        float p[8];
        p[0] = bflo((unsigned)w0); p[1] = bfhi((unsigned)w0);
        p[2] = bflo((unsigned)w1); p[3] = bfhi((unsigned)w1);
        p[4] = bflo((unsigned)w2); p[5] = bfhi((unsigned)w2);
        p[6] = bflo((unsigned)w3); p[7] = bfhi((unsigned)w3);

        // thread 0 owns global col 2 (word 1, low half): publish shift increment
        if (t == 0) s_D[par] = __logf(p[2]);

        // register GEMV: 16 rows x 8 cols, scalar FFMA
        float sv[ROWS];
        #pragma unroll
        for (int r = 0; r < ROWS; r++) {
            float a0 = E[r][0] * p[0];
            float a1 = E[r][1] * p[1];
            a0 = fmaf(E[r][2], p[2], a0);
            a1 = fmaf(E[r][3], p[3], a1);
            a0 = fmaf(E[r][4], p[4], a0);
            a1 = fmaf(E[r][5], p[5], a1);
            a0 = fmaf(E[r][6], p[6], a0);
            a1 = fmaf(E[r][7], p[7], a1);
            sv[r] = a0 + a1;
        }
        #pragma unroll
        for (int pr = 0; pr < 8; pr++)
            part2[par][pr * NTHR + t] = make_float2(sv[2 * pr], sv[2 * pr + 1]);
        __syncthreads();                                   // the ONLY per-step sync

        // warp w reduces row pair (2w, 2w+1) over all 256 thread-partials
        float2 acc = make_float2(0.f, 0.f);
        #pragma unroll
        for (int i = 0; i < NTHR / 32; i++) {
            float2 v = part2[par][w * NTHR + lane + 32 * i];
            acc.x += v.x; acc.y += v.y;
        }
        #pragma unroll
        for (int o = 16; o; o >>= 1) {
            acc.x += __shfl_xor_sync(~0u, acc.x, o);
            acc.y += __shfl_xor_sync(~0u, acc.y, o);
        }

        const float D = (s >= 2) ? s_D[par] : 0.0f;        // agreed shift increment
        Vacc += D;

        if (lane == 0) {
            // publish p_{s+1} = exp(log(acc) - D + rmax + emit), tag s+1, atomically
            float ex = __logf(acc.x) - D + myrmax.x + emit.x;
            float ey = __logf(acc.y) - D + myrmax.y + emit.y;
            unsigned pay = bfpack(__expf(ex), __expf(ey));
            unsigned long long word =
                ((unsigned long long)(unsigned)(s + 1) << 32) | pay;
            exch_rel(g_w[(s + 1) & 1] + 8 * b + w, word);
        }
        emit = emitN;
    }

    // ---- final: logsumexp(fv_S + trans[END=1, :]) on CTA 0 ----
    // fv_S[col] = log(p_S[col]) + V_{S-1};  Vacc == V_{S-1} here
    if (b == 0) {
        const float* trow = trans + TAGS;          // row END_IDX = 1
        float* sp = (float*)part2;                 // 32 KB scratch >= 8 KB needed
        const unsigned tgtS = (unsigned)S;
        float lm = -3.4e38f;
        #pragma unroll
        for (int k = 0; k < (NWORD / NTHR); k++) {
            int j = t + NTHR * k;                  // word index: cols 2j, 2j+1
            unsigned long long v;
            do { v = ldacq(g_w[S & 1] + j); } while (tag_of(v) != tgtS);
            float fa = __logf(bflo((unsigned)v)) + Vacc + __ldg(trow + 2 * j);
            float fb = __logf(bfhi((unsigned)v)) + Vacc + __ldg(trow + 2 * j + 1);
            sp[2 * j]     = fa;
            sp[2 * j + 1] = fb;
            lm = fmaxf(lm, fmaxf(fa, fb));
        }
        #pragma unroll
        for (int o = 16; o; o >>= 1) lm = fmaxf(lm, __shfl_xor_sync(~0u, lm, o));
        if (lane == 0) s_rmax[w] = lm;
        __syncthreads();
        float M = s_rmax[0];
        #pragma unroll
        for (int q = 1; q < 8; q++) M = fmaxf(M, s_rmax[q]);
        float sum = 0.f;
        #pragma unroll
        for (int k = 0; k < TAGS / NTHR; k++)
            sum += __expf(sp[t + NTHR * k] - M);
        #pragma unroll
        for (int o = 16; o; o >>= 1) sum += __shfl_xor_sync(~0u, sum, o);
        __syncthreads();
        if (lane == 0) s_rmax[w] = sum;
        __syncthreads();
        if (t == 0) {
            float tot = 0.f;
            #pragma unroll
            for (int q = 0; q < 8; q++) tot += s_rmax[q];
            out[0] = __logf(tot) + M;
        }
    }
}

// ---------------- launch ----------------------------------------------------
extern "C" void kernel_launch(void* const* d_in, const int* in_sizes, int n_in,
                              void* d_out, int out_size) {
    const float* h     = (const float*)d_in[0];
    const float* trans = (const float*)d_in[1];
    float* out = (float*)d_out;
    const int S = in_sizes[0] / TAGS;

    init_kernel<<<(NWORD + 255) / 256, 256>>>();
    crf_main<<<NCTA, NTHR>>>(h, trans, out, S);
}